// round 14
// baseline (speedup 1.0000x reference)
#include <cuda_runtime.h>
#include <cuda_bf16.h>
#include <cstdint>

#define DIM   768
#define INNER 96
#define NTOK  8
#define HW    1024
#define NB    64
#define EPS_LN 1e-5f

typedef unsigned long long ull;

// ---------------- scratch (device globals; no allocation allowed) ------------
__device__ uint2 g_Wfrag[48 * 12 * 32];   // B fragments, lane-ordered (147KB)
__device__ float g_colsum[INNER];
__device__ float g_bw1[INNER];
__device__ float g_r[NB * HW];
__device__ float g_mu[NB * HW];
__device__ float g_logitsT[NB * NTOK * HW];
__device__ float g_attnwT[NB * NTOK * HW];         // r_p * attn[p,n], [b][n][p]
__device__ float g_S[NB * NTOK];

// ---------------- helpers ----------------------------------------------------
__device__ __forceinline__ void mma_bf16(float* d,
    uint32_t a0, uint32_t a1, uint32_t a2, uint32_t a3,
    uint32_t b0, uint32_t b1)
{
    asm volatile(
        "mma.sync.aligned.m16n8k16.row.col.f32.bf16.bf16.f32 "
        "{%0,%1,%2,%3}, {%4,%5,%6,%7}, {%8,%9}, {%0,%1,%2,%3};"
        : "+f"(d[0]), "+f"(d[1]), "+f"(d[2]), "+f"(d[3])
        : "r"(a0), "r"(a1), "r"(a2), "r"(a3), "r"(b0), "r"(b1));
}

__device__ __forceinline__ uint32_t pack_bf16(float lo, float hi) {
    __nv_bfloat162 p = __floats2bfloat162_rn(lo, hi);
    return *(uint32_t*)&p;
}

// split fp32 pair -> hi bf16x2 + residual bf16x2
__device__ __forceinline__ void split2(float2 v, uint32_t& h, uint32_t& l) {
    __nv_bfloat162 hb = __floats2bfloat162_rn(v.x, v.y);
    uint32_t hu = *(uint32_t*)&hb;
    float f0 = __uint_as_float(hu << 16);
    float f1 = __uint_as_float(hu & 0xffff0000u);
    __nv_bfloat162 lb = __floats2bfloat162_rn(v.x - f0, v.y - f1);
    h = hu; l = *(uint32_t*)&lb;
}

// ---------------- setup: gamma-folded W1 -> lane-ordered B fragments ----------
__global__ void setup_kernel(const float* __restrict__ w1,
                             const float* __restrict__ gamma,
                             const float* __restrict__ beta,
                             const float* __restrict__ b1)
{
    int i = blockIdx.x;              // inner index 0..95
    int t = threadIdx.x;             // 256
    __shared__ float gw[DIM];
    float a = 0.f, bs = 0.f;
    for (int c = t; c < DIM; c += 256) {
        float w  = w1[c * INNER + i];
        float v  = gamma[c] * w;
        gw[c] = v;
        a  += v;
        bs += beta[c] * w;
    }
    __shared__ float ra[256], rb[256];
    ra[t] = a; rb[t] = bs;
    __syncthreads();
    for (int s = 128; s > 0; s >>= 1) {
        if (t < s) { ra[t] += ra[t + s]; rb[t] += rb[t + s]; }
        __syncthreads();
    }
    if (t == 0) { g_colsum[i] = ra[0]; g_bw1[i] = rb[0] + b1[i]; }

    // fragment lane layout: lane = g*4 + tid, g = i&7 (n-within-tile), tid = k-quarter
    int gg = i & 7, itile = i >> 3;
    if (t < 192) {
        int s = t >> 2, tid = t & 3;      // s = k16-step 0..47
        int c0 = s * 16 + 2 * tid;
        uint2 fr;
        fr.x = pack_bf16(gw[c0],     gw[c0 + 1]);
        fr.y = pack_bf16(gw[c0 + 8], gw[c0 + 9]);
        g_Wfrag[(s * 12 + itile) * 32 + gg * 4 + tid] = fr;
    }
}

// ---------------- pass A: register-direct bf16 mma, zero smem mainloop -------
__global__ __launch_bounds__(256, 2) void passA_kernel(
    const float* __restrict__ x, const float* __restrict__ w2)
{
    __shared__ float logitsS[128 * NTOK];
    __shared__ float sumS[128], sqS[128], muS[128], rS[128];
    __shared__ float w2S[INNER * NTOK];
    __shared__ float colsumS[INNER], bw1S[INNER];

    int t   = threadIdx.x;
    int blk = blockIdx.x;
    int b   = blk >> 3;
    int q0  = (blk & 7) << 7;

    for (int i = t; i < 128 * NTOK; i += 256) logitsS[i] = 0.f;
    for (int i = t; i < INNER * NTOK; i += 256) w2S[i] = w2[i];
    if (t < INNER) { colsumS[t] = g_colsum[t]; bw1S[t] = g_bw1[t]; }

    int w    = t >> 5, lane = t & 31;
    int wm   = w & 3,  wn   = w >> 2;   // warp tile: 32 tok x 48 i
    int g    = lane >> 2, tid = lane & 3;

    // A base: row (token) = q0 + wm*32 + g ; col (channel) = 2*tid + ...
    const float* xp = x + ((size_t)b * DIM + 2 * tid) * HW + q0 + wm * 32 + g;
    const uint2* bp = g_Wfrag + (wn * 6) * 32 + lane;

    float acc[2][6][4];
#pragma unroll
    for (int mt = 0; mt < 2; mt++)
#pragma unroll
        for (int nt = 0; nt < 6; nt++)
#pragma unroll
            for (int r = 0; r < 4; r++) acc[mt][nt][r] = 0.f;

    float s1[2] = {0.f, 0.f}, s2[2] = {0.f, 0.f};
    int sb = wn * 2;   // stats: wn=0 takes rows g (j 0,1,4,5), wn=1 rows g+8

    // A load offsets (floats): j0:(g,c+0)=0  j1:(g,c+1)=1024  j2:(g+8,c+0)=8
    //  j3:(g+8,c+1)=1032  j4:(g,c+8)=8192  j5:(g,c+9)=9216  j6:(g+8,c+8)=8200
    //  j7:(g+8,c+9)=9224 ; + mt*16
    float v[16];
#pragma unroll
    for (int mt = 0; mt < 2; mt++) {
        const float* p = xp + mt * 16;
        v[mt*8+0] = p[0];    v[mt*8+1] = p[1024];
        v[mt*8+2] = p[8];    v[mt*8+3] = p[1032];
        v[mt*8+4] = p[8192]; v[mt*8+5] = p[9216];
        v[mt*8+6] = p[8200]; v[mt*8+7] = p[9224];
    }
    xp += 16 * HW;

#pragma unroll 2
    for (int ks = 0; ks < 48; ks++) {
        float vn[16];
        if (ks < 47) {
#pragma unroll
            for (int mt = 0; mt < 2; mt++) {
                const float* p = xp + mt * 16;
                vn[mt*8+0] = p[0];    vn[mt*8+1] = p[1024];
                vn[mt*8+2] = p[8];    vn[mt*8+3] = p[1032];
                vn[mt*8+4] = p[8192]; vn[mt*8+5] = p[9216];
                vn[mt*8+6] = p[8200]; vn[mt*8+7] = p[9224];
            }
            xp += 16 * HW;
        }
        uint2 bv[6];
#pragma unroll
        for (int nt = 0; nt < 6; nt++) bv[nt] = bp[nt * 32];
        bp += 12 * 32;

        // stats on this warp's row-half
#pragma unroll
        for (int mt = 0; mt < 2; mt++) {
            float x0 = v[mt*8 + sb + 0], x1 = v[mt*8 + sb + 1];
            float x4 = v[mt*8 + sb + 4], x5 = v[mt*8 + sb + 5];
            s1[mt] += (x0 + x1) + (x4 + x5);
            s2[mt] += x0 * x0 + x1 * x1 + x4 * x4 + x5 * x5;
        }
        // convert to A fragments
        uint32_t a[2][4];
#pragma unroll
        for (int mt = 0; mt < 2; mt++) {
            a[mt][0] = pack_bf16(v[mt*8+0], v[mt*8+1]);   // row g,   k0..1
            a[mt][1] = pack_bf16(v[mt*8+2], v[mt*8+3]);   // row g+8, k0..1
            a[mt][2] = pack_bf16(v[mt*8+4], v[mt*8+5]);   // row g,   k8..9
            a[mt][3] = pack_bf16(v[mt*8+6], v[mt*8+7]);   // row g+8, k8..9
        }
#pragma unroll
        for (int nt = 0; nt < 6; nt++) {
            mma_bf16(acc[0][nt], a[0][0], a[0][1], a[0][2], a[0][3],
                     bv[nt].x, bv[nt].y);
            mma_bf16(acc[1][nt], a[1][0], a[1][1], a[1][2], a[1][3],
                     bv[nt].x, bv[nt].y);
        }
#pragma unroll
        for (int j = 0; j < 16; j++) v[j] = vn[j];
    }

    // stats: reduce over tid (lanes xor 1, 2), direct store (unique rows)
#pragma unroll
    for (int mt = 0; mt < 2; mt++) {
        s1[mt] += __shfl_xor_sync(0xffffffffu, s1[mt], 1);
        s1[mt] += __shfl_xor_sync(0xffffffffu, s1[mt], 2);
        s2[mt] += __shfl_xor_sync(0xffffffffu, s2[mt], 1);
        s2[mt] += __shfl_xor_sync(0xffffffffu, s2[mt], 2);
    }
    if (tid == 0) {
#pragma unroll
        for (int mt = 0; mt < 2; mt++) {
            int row = wm * 32 + mt * 16 + wn * 8 + g;
            sumS[row] = s1[mt];
            sqS[row]  = s2[mt];
        }
    }
    __syncthreads();
    if (t < 128) {
        float mu  = sumS[t] * (1.f / DIM);
        float var = sqS[t] * (1.f / DIM) - mu * mu;
        float r   = rsqrtf(var + EPS_LN);
        muS[t] = mu; rS[t] = r;
        g_mu[b * HW + q0 + t] = mu;
        g_r [b * HW + q0 + t] = r;
    }
    __syncthreads();

    // epilogue: y -> gelu -> logits
#pragma unroll
    for (int mt = 0; mt < 2; mt++) {
#pragma unroll
        for (int hf = 0; hf < 2; hf++) {
            int ql   = wm * 32 + mt * 16 + hf * 8 + g;
            float mu = muS[ql], r = rS[ql];
            float pl[NTOK];
#pragma unroll
            for (int n = 0; n < NTOK; n++) pl[n] = 0.f;
#pragma unroll
            for (int nt = 0; nt < 6; nt++) {
#pragma unroll
                for (int ch = 0; ch < 2; ch++) {
                    int i   = wn * 48 + nt * 8 + tid * 2 + ch;
                    float vv = acc[mt][nt][hf * 2 + ch];
                    float y  = r * (vv - mu * colsumS[i]) + bw1S[i];
                    float h  = 0.5f * y * (1.f + erff(y * 0.70710678f));
#pragma unroll
                    for (int n = 0; n < NTOK; n++) pl[n] += h * w2S[i * NTOK + n];
                }
            }
#pragma unroll
            for (int n = 0; n < NTOK; n++) {
                pl[n] += __shfl_xor_sync(0xffffffffu, pl[n], 1);
                pl[n] += __shfl_xor_sync(0xffffffffu, pl[n], 2);
            }
            if (tid == 0) {
#pragma unroll
                for (int n = 0; n < NTOK; n++)
                    atomicAdd(&logitsS[ql * NTOK + n], pl[n]);
            }
        }
    }
    __syncthreads();
    for (int idx = t; idx < 128 * NTOK; idx += 256) {
        int n = idx >> 7, q = idx & 127;
        g_logitsT[((size_t)b * NTOK + n) * HW + q0 + q] = logitsS[q * NTOK + n];
    }
}

// ---------------- pass B: softmax over tokens, per (b, n) --------------------
__global__ void passB_kernel()
{
    int b = blockIdx.x;
    int w = threadIdx.x >> 5, lane = threadIdx.x & 31;
    const float* lp  = g_logitsT + ((size_t)b * NTOK + w) * HW;
    const float* mup = g_mu + (size_t)b * HW;
    const float* rp  = g_r  + (size_t)b * HW;

    float m = -1e30f;
    for (int j = 0; j < 32; j++) m = fmaxf(m, lp[lane + j * 32]);
#pragma unroll
    for (int o = 16; o; o >>= 1) m = fmaxf(m, __shfl_xor_sync(0xffffffffu, m, o));

    float Z = 0.f, Sm = 0.f;
    for (int j = 0; j < 32; j++) {
        int p  = lane + j * 32;
        float e = expf(lp[p] - m);
        Z  += e;
        Sm += mup[p] * rp[p] * e;
    }
#pragma unroll
    for (int o = 16; o; o >>= 1) {
        Z  += __shfl_xor_sync(0xffffffffu, Z,  o);
        Sm += __shfl_xor_sync(0xffffffffu, Sm, o);
    }
    float invZ = 1.f / Z;
    float* ap = g_attnwT + ((size_t)b * NTOK + w) * HW;
    for (int j = 0; j < 32; j++) {
        int p  = lane + j * 32;
        float e = expf(lp[p] - m);
        ap[p] = rp[p] * e * invZ;
    }
    if (lane == 0) g_S[b * NTOK + w] = Sm * invZ;
}

// ---------------- pass C (R7 form): register-direct split-bf16 MMA -----------
struct KData { float2 a0, a1, a2, a3, b0, b1; };

__device__ __forceinline__ void ld_k(KData& d, const float* xr, const float* xr8,
                                     const float* br, int k0)
{
    d.a0 = *(const float2*)(xr  + k0);
    d.a1 = *(const float2*)(xr8 + k0);
    d.a2 = *(const float2*)(xr  + k0 + 8);
    d.a3 = *(const float2*)(xr8 + k0 + 8);
    d.b0 = *(const float2*)(br  + k0);
    d.b1 = *(const float2*)(br  + k0 + 8);
}

__global__ __launch_bounds__(256) void passC_kernel(
    const float* __restrict__ x, const float* __restrict__ gamma,
    const float* __restrict__ beta, float* __restrict__ out)
{
    int t = threadIdx.x, w = t >> 5, lane = t & 31;
    int blk  = blockIdx.x;
    int b    = blk / 6;
    int slab = blk % 6;

    int g  = lane >> 2;          // row-group (A rows / B col n)
    int tq = (lane & 3) * 2;     // k-pair offset

    int cw = slab * 128 + w * 16;
    const float* xr  = x + ((size_t)b * DIM + cw + g) * HW + tq;
    const float* xr8 = xr + 8 * HW;
    const float* br  = g_attnwT + ((size_t)b * NTOK + g) * HW + tq;

    float acc[4]  = {0.f, 0.f, 0.f, 0.f};
    float acc2[4] = {0.f, 0.f, 0.f, 0.f};

    KData buf[2];
    ld_k(buf[0], xr, xr8, br, 0);
    ld_k(buf[1], xr, xr8, br, 16);

#pragma unroll 2
    for (int ks = 0; ks < 64; ks++) {
        KData cur = buf[ks & 1];
        if (ks < 62) ld_k(buf[ks & 1], xr, xr8, br, (ks + 2) * 16);

        uint32_t ah0, ah1, ah2, ah3, al0, al1, al2, al3;
        uint32_t bh0, bh1, bl0, bl1;
        split2(cur.a0, ah0, al0);
        split2(cur.a1, ah1, al1);
        split2(cur.a2, ah2, al2);
        split2(cur.a3, ah3, al3);
        split2(cur.b0, bh0, bl0);
        split2(cur.b1, bh1, bl1);

        mma_bf16(acc,  ah0, ah1, ah2, ah3, bh0, bh1);
        mma_bf16(acc2, ah0, ah1, ah2, ah3, bl0, bl1);
        mma_bf16(acc,  al0, al1, al2, al3, bh0, bh1);
    }

    int n0 = (lane & 3) * 2;
    float S0 = g_S[b * NTOK + n0];
    float S1 = g_S[b * NTOK + n0 + 1];
    int m0 = lane >> 2;
#pragma unroll
    for (int half = 0; half < 2; half++) {
        int c = cw + m0 + half * 8;
        float gm = gamma[c], be = beta[c];
        float v0 = acc[half * 2 + 0] + acc2[half * 2 + 0];
        float v1 = acc[half * 2 + 1] + acc2[half * 2 + 1];
        float2 o;
        o.x = (gm * (v0 - S0) + be) * (1.f / 1024.f);
        o.y = (gm * (v1 - S1) + be) * (1.f / 1024.f);
        *(float2*)&out[(((size_t)b * DIM) + c) * NTOK + n0] = o;
    }
}

// ---------------- launcher ----------------------------------------------------
extern "C" void kernel_launch(void* const* d_in, const int* in_sizes, int n_in,
                              void* d_out, int out_size)
{
    const float* x     = (const float*)d_in[0];
    const float* gamma = (const float*)d_in[1];
    const float* beta  = (const float*)d_in[2];
    const float* w1    = (const float*)d_in[3];
    const float* b1    = (const float*)d_in[4];
    const float* w2    = (const float*)d_in[5];
    // d_in[6] = b2: constant shift before token softmax -> cancels exactly.
    float* out = (float*)d_out;

    setup_kernel<<<INNER, 256>>>(w1, gamma, beta, b1);
    passA_kernel<<<NB * 8, 256>>>(x, w2);
    passB_kernel<<<NB, 256>>>();
    passC_kernel<<<NB * 6, 256>>>(x, gamma, beta, out);
}

// round 15
// speedup vs baseline: 1.0018x; 1.0018x over previous
#include <cuda_runtime.h>
#include <cuda_bf16.h>
#include <cstdint>

#define DIM   768
#define INNER 96
#define NTOK  8
#define HW    1024
#define NB    64
#define EPS_LN 1e-5f

typedef unsigned long long ull;

// ---------------- scratch (device globals; no allocation allowed) ------------
__device__ uint2 g_Wfrag[48 * 12 * 32];   // B fragments, lane-ordered (147KB)
__device__ float g_colsum[INNER];
__device__ float g_bw1[INNER];
__device__ float g_r[NB * HW];
__device__ float g_mu[NB * HW];
__device__ float g_logitsT[NB * NTOK * HW];
__device__ float g_attnwT[NB * NTOK * HW];         // r_p * attn[p,n], [b][n][p]
__device__ float g_S[NB * NTOK];

// ---------------- helpers ----------------------------------------------------
__device__ __forceinline__ void mma_bf16(float* d,
    uint32_t a0, uint32_t a1, uint32_t a2, uint32_t a3,
    uint32_t b0, uint32_t b1)
{
    asm volatile(
        "mma.sync.aligned.m16n8k16.row.col.f32.bf16.bf16.f32 "
        "{%0,%1,%2,%3}, {%4,%5,%6,%7}, {%8,%9}, {%0,%1,%2,%3};"
        : "+f"(d[0]), "+f"(d[1]), "+f"(d[2]), "+f"(d[3])
        : "r"(a0), "r"(a1), "r"(a2), "r"(a3), "r"(b0), "r"(b1));
}

__device__ __forceinline__ void ldsm_x4(uint32_t* r, uint32_t addr) {
    asm volatile("ldmatrix.sync.aligned.m8n8.x4.shared.b16 {%0,%1,%2,%3}, [%4];"
        : "=r"(r[0]), "=r"(r[1]), "=r"(r[2]), "=r"(r[3]) : "r"(addr));
}

__device__ __forceinline__ uint32_t pack_bf16(float lo, float hi) {
    __nv_bfloat162 p = __floats2bfloat162_rn(lo, hi);
    return *(uint32_t*)&p;
}

// split fp32 pair -> hi bf16x2 + residual bf16x2
__device__ __forceinline__ void split2(float2 v, uint32_t& h, uint32_t& l) {
    __nv_bfloat162 hb = __floats2bfloat162_rn(v.x, v.y);
    uint32_t hu = *(uint32_t*)&hb;
    float f0 = __uint_as_float(hu << 16);
    float f1 = __uint_as_float(hu & 0xffff0000u);
    __nv_bfloat162 lb = __floats2bfloat162_rn(v.x - f0, v.y - f1);
    h = hu; l = *(uint32_t*)&lb;
}

// ---------------- setup: gamma-folded W1 -> lane-ordered B fragments ----------
__global__ void setup_kernel(const float* __restrict__ w1,
                             const float* __restrict__ gamma,
                             const float* __restrict__ beta,
                             const float* __restrict__ b1)
{
    int i = blockIdx.x;              // inner index 0..95
    int t = threadIdx.x;             // 256
    __shared__ float gw[DIM];
    float a = 0.f, bs = 0.f;
    for (int c = t; c < DIM; c += 256) {
        float w  = w1[c * INNER + i];
        float v  = gamma[c] * w;
        gw[c] = v;
        a  += v;
        bs += beta[c] * w;
    }
    __shared__ float ra[256], rb[256];
    ra[t] = a; rb[t] = bs;
    __syncthreads();
    for (int s = 128; s > 0; s >>= 1) {
        if (t < s) { ra[t] += ra[t + s]; rb[t] += rb[t + s]; }
        __syncthreads();
    }
    if (t == 0) { g_colsum[i] = ra[0]; g_bw1[i] = rb[0] + b1[i]; }

    // fragment lane layout: lane = g*4 + tid, g = i&7 (n-within-tile), tid = k-quarter
    int gg = i & 7, itile = i >> 3;
    if (t < 192) {
        int s = t >> 2, tid = t & 3;      // s = k16-step 0..47
        int c0 = s * 16 + 2 * tid;
        uint2 fr;
        fr.x = pack_bf16(gw[c0],     gw[c0 + 1]);
        fr.y = pack_bf16(gw[c0 + 8], gw[c0 + 9]);
        g_Wfrag[(s * 12 + itile) * 32 + gg * 4 + tid] = fr;
    }
}

// ---------------- pass A: smem X pipeline + global B fragments ---------------
constexpr int XP = 40;

__global__ __launch_bounds__(256, 3) void passA_kernel(
    const float* __restrict__ x, const float* __restrict__ w2)
{
    __shared__ __nv_bfloat16 Xs[2][128 * XP];   // 20480 B
    __shared__ float logitsS[128 * NTOK];
    __shared__ float sumS[128], sqS[128], muS[128], rS[128];
    __shared__ float w2S[INNER * NTOK];
    __shared__ float colsumS[INNER], bw1S[INNER];

    int t   = threadIdx.x;
    int blk = blockIdx.x;
    int b   = blk >> 3;
    int q0  = (blk & 7) << 7;

    for (int i = t; i < 128 * NTOK; i += 256) logitsS[i] = 0.f;
    if (t < 128) { sumS[t] = 0.f; sqS[t] = 0.f; }
    for (int i = t; i < INNER * NTOK; i += 256) w2S[i] = w2[i];
    if (t < INNER) { colsumS[t] = g_colsum[t]; bw1S[t] = g_bw1[t]; }

    int qi = t & 63;           // token pair: rows 2qi, 2qi+1
    int ci = t >> 6;           // channel slice 0..3 (8 channels each)
    const float* xb = x + ((size_t)b * DIM) * HW + q0 + qi * 2;

    float s1a = 0.f, s1b = 0.f, s2a = 0.f, s2b = 0.f;
    float acc[2][6][4];
#pragma unroll
    for (int mt = 0; mt < 2; mt++)
#pragma unroll
        for (int nt = 0; nt < 6; nt++)
#pragma unroll
            for (int r = 0; r < 4; r++) acc[mt][nt][r] = 0.f;

    int w    = t >> 5, lane = t & 31;
    int wm   = w & 3,  wn   = w >> 2;   // warp tile: 32 tok x 48 i
    int gid  = lane >> 2, tid = lane & 3;

    uint32_t aAddr0 = (uint32_t)__cvta_generic_to_shared(
        &Xs[0][(wm * 32 + (lane & 15)) * XP + (lane >> 4) * 8]);
    uint32_t aAddr1 = aAddr0 + 16 * XP * 2;
    const uint32_t XBUF = 128 * XP * 2;

    // B fragments straight from g_Wfrag (L1/L2 resident, layout verified R13)
    const uint2* bp = g_Wfrag + (wn * 6) * 32 + lane;

    float2 xv[8];
#pragma unroll
    for (int j = 0; j < 8; j++)
        xv[j] = *(const float2*)(xb + (size_t)(ci * 8 + j) * HW);

    for (int kc = 0; kc < 24; kc++) {
        int buf = kc & 1;
#pragma unroll
        for (int j = 0; j < 8; j++) {
            s1a += xv[j].x; s2a += xv[j].x * xv[j].x;
            s1b += xv[j].y; s2b += xv[j].y * xv[j].y;
        }
        __nv_bfloat162 p0[4], p1[4];
#pragma unroll
        for (int j = 0; j < 4; j++) {
            p0[j] = __floats2bfloat162_rn(xv[2*j].x, xv[2*j+1].x);
            p1[j] = __floats2bfloat162_rn(xv[2*j].y, xv[2*j+1].y);
        }
        *(uint4*)&Xs[buf][(qi * 2)     * XP + ci * 8] = *(uint4*)p0;
        *(uint4*)&Xs[buf][(qi * 2 + 1) * XP + ci * 8] = *(uint4*)p1;

        // hoisted X prefetch for kc+1 (regs consumed; overlaps barrier drain)
        if (kc < 23) {
            int c0 = (kc + 1) * 32;
#pragma unroll
            for (int j = 0; j < 8; j++)
                xv[j] = *(const float2*)(xb + (size_t)(c0 + ci * 8 + j) * HW);
        }
        __syncthreads();

        uint32_t xo = buf * XBUF;
#pragma unroll
        for (int ks = 0; ks < 2; ks++) {
            uint32_t af0[4], af1[4];
            ldsm_x4(af0, aAddr0 + xo + ks * 32);
            ldsm_x4(af1, aAddr1 + xo + ks * 32);
            const uint2* bks = bp + (size_t)(kc * 2 + ks) * 12 * 32;
#pragma unroll
            for (int nt = 0; nt < 6; nt++) {
                uint2 bv = bks[nt * 32];
                mma_bf16(acc[0][nt], af0[0], af0[1], af0[2], af0[3], bv.x, bv.y);
                mma_bf16(acc[1][nt], af1[0], af1[1], af1[2], af1[3], bv.x, bv.y);
            }
        }
    }

    // token stats
    atomicAdd(&sumS[qi * 2],     s1a); atomicAdd(&sqS[qi * 2],     s2a);
    atomicAdd(&sumS[qi * 2 + 1], s1b); atomicAdd(&sqS[qi * 2 + 1], s2b);
    __syncthreads();
    if (t < 128) {
        float mu  = sumS[t] * (1.f / DIM);
        float var = sqS[t] * (1.f / DIM) - mu * mu;
        float r   = rsqrtf(var + EPS_LN);
        muS[t] = mu; rS[t] = r;
        g_mu[b * HW + q0 + t] = mu;
        g_r [b * HW + q0 + t] = r;
    }
    __syncthreads();

    // epilogue: y -> gelu -> logits
#pragma unroll
    for (int mt = 0; mt < 2; mt++) {
#pragma unroll
        for (int hf = 0; hf < 2; hf++) {
            int ql   = wm * 32 + mt * 16 + hf * 8 + gid;
            float mu = muS[ql], r = rS[ql];
            float pl[NTOK];
#pragma unroll
            for (int n = 0; n < NTOK; n++) pl[n] = 0.f;
#pragma unroll
            for (int nt = 0; nt < 6; nt++) {
#pragma unroll
                for (int ch = 0; ch < 2; ch++) {
                    int i   = wn * 48 + nt * 8 + tid * 2 + ch;
                    float v = acc[mt][nt][hf * 2 + ch];
                    float y = r * (v - mu * colsumS[i]) + bw1S[i];
                    float h = 0.5f * y * (1.f + erff(y * 0.70710678f));
#pragma unroll
                    for (int n = 0; n < NTOK; n++) pl[n] += h * w2S[i * NTOK + n];
                }
            }
#pragma unroll
            for (int n = 0; n < NTOK; n++) {
                pl[n] += __shfl_xor_sync(0xffffffffu, pl[n], 1);
                pl[n] += __shfl_xor_sync(0xffffffffu, pl[n], 2);
            }
            if (tid == 0) {
#pragma unroll
                for (int n = 0; n < NTOK; n++)
                    atomicAdd(&logitsS[ql * NTOK + n], pl[n]);
            }
        }
    }
    __syncthreads();
    for (int idx = t; idx < 128 * NTOK; idx += 256) {
        int n = idx >> 7, q = idx & 127;
        g_logitsT[((size_t)b * NTOK + n) * HW + q0 + q] = logitsS[q * NTOK + n];
    }
}

// ---------------- pass B: softmax over tokens, per (b, n) --------------------
__global__ void passB_kernel()
{
    int b = blockIdx.x;
    int w = threadIdx.x >> 5, lane = threadIdx.x & 31;
    const float* lp  = g_logitsT + ((size_t)b * NTOK + w) * HW;
    const float* mup = g_mu + (size_t)b * HW;
    const float* rp  = g_r  + (size_t)b * HW;

    float m = -1e30f;
    for (int j = 0; j < 32; j++) m = fmaxf(m, lp[lane + j * 32]);
#pragma unroll
    for (int o = 16; o; o >>= 1) m = fmaxf(m, __shfl_xor_sync(0xffffffffu, m, o));

    float Z = 0.f, Sm = 0.f;
    for (int j = 0; j < 32; j++) {
        int p  = lane + j * 32;
        float e = expf(lp[p] - m);
        Z  += e;
        Sm += mup[p] * rp[p] * e;
    }
#pragma unroll
    for (int o = 16; o; o >>= 1) {
        Z  += __shfl_xor_sync(0xffffffffu, Z,  o);
        Sm += __shfl_xor_sync(0xffffffffu, Sm, o);
    }
    float invZ = 1.f / Z;
    float* ap = g_attnwT + ((size_t)b * NTOK + w) * HW;
    for (int j = 0; j < 32; j++) {
        int p  = lane + j * 32;
        float e = expf(lp[p] - m);
        ap[p] = rp[p] * e * invZ;
    }
    if (lane == 0) g_S[b * NTOK + w] = Sm * invZ;
}

// ---------------- pass C (R7 form): register-direct split-bf16 MMA -----------
struct KData { float2 a0, a1, a2, a3, b0, b1; };

__device__ __forceinline__ void ld_k(KData& d, const float* xr, const float* xr8,
                                     const float* br, int k0)
{
    d.a0 = *(const float2*)(xr  + k0);
    d.a1 = *(const float2*)(xr8 + k0);
    d.a2 = *(const float2*)(xr  + k0 + 8);
    d.a3 = *(const float2*)(xr8 + k0 + 8);
    d.b0 = *(const float2*)(br  + k0);
    d.b1 = *(const float2*)(br  + k0 + 8);
}

__global__ __launch_bounds__(256) void passC_kernel(
    const float* __restrict__ x, const float* __restrict__ gamma,
    const float* __restrict__ beta, float* __restrict__ out)
{
    int t = threadIdx.x, w = t >> 5, lane = t & 31;
    int blk  = blockIdx.x;
    int b    = blk / 6;
    int slab = blk % 6;

    int g  = lane >> 2;          // row-group (A rows / B col n)
    int tq = (lane & 3) * 2;     // k-pair offset

    int cw = slab * 128 + w * 16;
    const float* xr  = x + ((size_t)b * DIM + cw + g) * HW + tq;
    const float* xr8 = xr + 8 * HW;
    const float* br  = g_attnwT + ((size_t)b * NTOK + g) * HW + tq;

    float acc[4]  = {0.f, 0.f, 0.f, 0.f};
    float acc2[4] = {0.f, 0.f, 0.f, 0.f};

    KData buf[2];
    ld_k(buf[0], xr, xr8, br, 0);
    ld_k(buf[1], xr, xr8, br, 16);

#pragma unroll 2
    for (int ks = 0; ks < 64; ks++) {
        KData cur = buf[ks & 1];
        if (ks < 62) ld_k(buf[ks & 1], xr, xr8, br, (ks + 2) * 16);

        uint32_t ah0, ah1, ah2, ah3, al0, al1, al2, al3;
        uint32_t bh0, bh1, bl0, bl1;
        split2(cur.a0, ah0, al0);
        split2(cur.a1, ah1, al1);
        split2(cur.a2, ah2, al2);
        split2(cur.a3, ah3, al3);
        split2(cur.b0, bh0, bl0);
        split2(cur.b1, bh1, bl1);

        mma_bf16(acc,  ah0, ah1, ah2, ah3, bh0, bh1);
        mma_bf16(acc2, ah0, ah1, ah2, ah3, bl0, bl1);
        mma_bf16(acc,  al0, al1, al2, al3, bh0, bh1);
    }

    int n0 = (lane & 3) * 2;
    float S0 = g_S[b * NTOK + n0];
    float S1 = g_S[b * NTOK + n0 + 1];
    int m0 = lane >> 2;
#pragma unroll
    for (int half = 0; half < 2; half++) {
        int c = cw + m0 + half * 8;
        float gm = gamma[c], be = beta[c];
        float v0 = acc[half * 2 + 0] + acc2[half * 2 + 0];
        float v1 = acc[half * 2 + 1] + acc2[half * 2 + 1];
        float2 o;
        o.x = (gm * (v0 - S0) + be) * (1.f / 1024.f);
        o.y = (gm * (v1 - S1) + be) * (1.f / 1024.f);
        *(float2*)&out[(((size_t)b * DIM) + c) * NTOK + n0] = o;
    }
}

// ---------------- launcher ----------------------------------------------------
extern "C" void kernel_launch(void* const* d_in, const int* in_sizes, int n_in,
                              void* d_out, int out_size)
{
    const float* x     = (const float*)d_in[0];
    const float* gamma = (const float*)d_in[1];
    const float* beta  = (const float*)d_in[2];
    const float* w1    = (const float*)d_in[3];
    const float* b1    = (const float*)d_in[4];
    const float* w2    = (const float*)d_in[5];
    // d_in[6] = b2: constant shift before token softmax -> cancels exactly.
    float* out = (float*)d_out;

    setup_kernel<<<INNER, 256>>>(w1, gamma, beta, b1);
    passA_kernel<<<NB * 8, 256>>>(x, w2);
    passB_kernel<<<NB, 256>>>();
    passC_kernel<<<NB * 6, 256>>>(x, gamma, beta, out);
}

// round 16
// speedup vs baseline: 1.3095x; 1.3071x over previous
#include <cuda_runtime.h>
#include <cuda_bf16.h>
#include <cstdint>

#define DIM   768
#define INNER 96
#define NTOK  8
#define HW    1024
#define NB    64
#define EPS_LN 1e-5f

typedef unsigned long long ull;

// ---------------- scratch (device globals; no allocation allowed) ------------
__device__ __nv_bfloat16 g_Wt[INNER * DIM];        // W1*gamma, bf16, [i][c]
__device__ float g_colsum[INNER];
__device__ float g_bw1[INNER];
__device__ float g_r[NB * HW];
__device__ float g_mu[NB * HW];
__device__ float g_logitsT[NB * NTOK * HW];
__device__ __nv_bfloat16 g_awH[NB * NTOK * HW];    // hi(r*attn), [b][n][q]
__device__ __nv_bfloat16 g_awL[NB * NTOK * HW];    // residual,   [b][n][q]
__device__ float g_S[NB * NTOK];

// ---------------- helpers ----------------------------------------------------
__device__ __forceinline__ void mma_bf16(float* d,
    uint32_t a0, uint32_t a1, uint32_t a2, uint32_t a3,
    uint32_t b0, uint32_t b1)
{
    asm volatile(
        "mma.sync.aligned.m16n8k16.row.col.f32.bf16.bf16.f32 "
        "{%0,%1,%2,%3}, {%4,%5,%6,%7}, {%8,%9}, {%0,%1,%2,%3};"
        : "+f"(d[0]), "+f"(d[1]), "+f"(d[2]), "+f"(d[3])
        : "r"(a0), "r"(a1), "r"(a2), "r"(a3), "r"(b0), "r"(b1));
}

__device__ __forceinline__ void ldsm_x4(uint32_t* r, uint32_t addr) {
    asm volatile("ldmatrix.sync.aligned.m8n8.x4.shared.b16 {%0,%1,%2,%3}, [%4];"
        : "=r"(r[0]), "=r"(r[1]), "=r"(r[2]), "=r"(r[3]) : "r"(addr));
}

// split fp32 pair -> hi bf16x2 + residual bf16x2
__device__ __forceinline__ void split2(float2 v, uint32_t& h, uint32_t& l) {
    __nv_bfloat162 hb = __floats2bfloat162_rn(v.x, v.y);
    uint32_t hu = *(uint32_t*)&hb;
    float f0 = __uint_as_float(hu << 16);
    float f1 = __uint_as_float(hu & 0xffff0000u);
    __nv_bfloat162 lb = __floats2bfloat162_rn(v.x - f0, v.y - f1);
    h = hu; l = *(uint32_t*)&lb;
}

// ---------------- setup: fold gamma into W1, precompute column sums ----------
__global__ void setup_kernel(const float* __restrict__ w1,
                             const float* __restrict__ gamma,
                             const float* __restrict__ beta,
                             const float* __restrict__ b1)
{
    int i = blockIdx.x;
    int t = threadIdx.x;
    float a = 0.f, bs = 0.f;
    for (int c = t; c < DIM; c += 256) {
        float w  = w1[c * INNER + i];
        float gw = gamma[c] * w;
        g_Wt[i * DIM + c] = __float2bfloat16(gw);
        a  += gw;
        bs += beta[c] * w;
    }
    __shared__ float ra[256], rb[256];
    ra[t] = a; rb[t] = bs;
    __syncthreads();
    for (int s = 128; s > 0; s >>= 1) {
        if (t < s) { ra[t] += ra[t + s]; rb[t] += rb[t + s]; }
        __syncthreads();
    }
    if (t == 0) { g_colsum[i] = ra[0]; g_bw1[i] = rb[0] + b1[i]; }
}

// ---------------- pass A (R12 form): smem pipeline, hoisted prefetch ---------
constexpr int XP = 40;
constexpr int WP = 40;

__global__ __launch_bounds__(256, 2) void passA_kernel(
    const float* __restrict__ x, const float* __restrict__ w2)
{
    __shared__ __nv_bfloat16 Xs[2][128 * XP];
    __shared__ __nv_bfloat16 Ws[2][INNER * WP];
    __shared__ float logitsS[128 * NTOK];
    __shared__ float sumS[128], sqS[128], muS[128], rS[128];
    __shared__ float w2S[INNER * NTOK];
    __shared__ float colsumS[INNER], bw1S[INNER];

    int t   = threadIdx.x;
    int blk = blockIdx.x;
    int b   = blk >> 3;
    int q0  = (blk & 7) << 7;

    for (int i = t; i < 128 * NTOK; i += 256) logitsS[i] = 0.f;
    if (t < 128) { sumS[t] = 0.f; sqS[t] = 0.f; }
    for (int i = t; i < INNER * NTOK; i += 256) w2S[i] = w2[i];
    if (t < INNER) { colsumS[t] = g_colsum[t]; bw1S[t] = g_bw1[t]; }

    int qi = t & 63;           // token pair: rows 2qi, 2qi+1
    int ci = t >> 6;           // channel slice 0..3 (8 channels each)
    const float* xb = x + ((size_t)b * DIM) * HW + q0 + qi * 2;

    float s1a = 0.f, s1b = 0.f, s2a = 0.f, s2b = 0.f;
    float acc[2][6][4];
#pragma unroll
    for (int mt = 0; mt < 2; mt++)
#pragma unroll
        for (int nt = 0; nt < 6; nt++)
#pragma unroll
            for (int r = 0; r < 4; r++) acc[mt][nt][r] = 0.f;

    int w    = t >> 5, lane = t & 31;
    int wm   = w & 3,  wn   = w >> 2;   // warp tile: 32 tok x 48 i
    int gid  = lane >> 2, tid = lane & 3;
    int wi   = t >> 1, whf = t & 1;     // W loader (t<192): row wi, 16-ch half

    uint32_t aAddr0 = (uint32_t)__cvta_generic_to_shared(
        &Xs[0][(wm * 32 + (lane & 15)) * XP + (lane >> 4) * 8]);
    uint32_t aAddr1 = aAddr0 + 16 * XP * 2;
    // B ldmatrix.x4: lanes 0-7 -> [n0..7, k0-7], 8-15 -> [n0..7, k8-15],
    //                16-23 -> [n8..15, k0-7], 24-31 -> [n8..15, k8-15]
    uint32_t bAddr4 = (uint32_t)__cvta_generic_to_shared(
        &Ws[0][(wn * 48 + (lane >> 4) * 8 + (lane & 7)) * WP + ((lane >> 3) & 1) * 8]);
    const uint32_t XBUF = 128 * XP * 2;
    const uint32_t WBUF = INNER * WP * 2;

    float2 xv[8];
    uint4 wv0, wv1;
#pragma unroll
    for (int j = 0; j < 8; j++)
        xv[j] = *(const float2*)(xb + (size_t)(ci * 8 + j) * HW);
    if (t < 192) {
        const uint4* src = (const uint4*)(g_Wt + wi * DIM + whf * 16);
        wv0 = src[0]; wv1 = src[1];
    }

    for (int kc = 0; kc < 24; kc++) {
        int buf = kc & 1;
#pragma unroll
        for (int j = 0; j < 8; j++) {
            s1a += xv[j].x; s2a += xv[j].x * xv[j].x;
            s1b += xv[j].y; s2b += xv[j].y * xv[j].y;
        }
        __nv_bfloat162 p0[4], p1[4];
#pragma unroll
        for (int j = 0; j < 4; j++) {
            p0[j] = __floats2bfloat162_rn(xv[2*j].x, xv[2*j+1].x);
            p1[j] = __floats2bfloat162_rn(xv[2*j].y, xv[2*j+1].y);
        }
        *(uint4*)&Xs[buf][(qi * 2)     * XP + ci * 8] = *(uint4*)p0;
        *(uint4*)&Xs[buf][(qi * 2 + 1) * XP + ci * 8] = *(uint4*)p1;
        if (t < 192) {
            uint4* dst = (uint4*)&Ws[buf][wi * WP + whf * 16];
            dst[0] = wv0; dst[1] = wv1;
        }

        // hoisted prefetch for kc+1 (regs consumed; overlaps barrier drain)
        if (kc < 23) {
            int c0 = (kc + 1) * 32;
#pragma unroll
            for (int j = 0; j < 8; j++)
                xv[j] = *(const float2*)(xb + (size_t)(c0 + ci * 8 + j) * HW);
            if (t < 192) {
                const uint4* src = (const uint4*)(g_Wt + wi * DIM + c0 + whf * 16);
                wv0 = src[0]; wv1 = src[1];
            }
        }
        __syncthreads();

        uint32_t xo = buf * XBUF, wo = buf * WBUF;
#pragma unroll
        for (int ks = 0; ks < 2; ks++) {
            uint32_t af0[4], af1[4];
            ldsm_x4(af0, aAddr0 + xo + ks * 32);
            ldsm_x4(af1, aAddr1 + xo + ks * 32);
            uint32_t bf[3][4];
#pragma unroll
            for (int p = 0; p < 3; p++)
                ldsm_x4(bf[p], bAddr4 + wo + p * 16 * WP * 2 + ks * 32);
#pragma unroll
            for (int p = 0; p < 3; p++) {
                mma_bf16(acc[0][2*p],   af0[0], af0[1], af0[2], af0[3], bf[p][0], bf[p][1]);
                mma_bf16(acc[1][2*p],   af1[0], af1[1], af1[2], af1[3], bf[p][0], bf[p][1]);
                mma_bf16(acc[0][2*p+1], af0[0], af0[1], af0[2], af0[3], bf[p][2], bf[p][3]);
                mma_bf16(acc[1][2*p+1], af1[0], af1[1], af1[2], af1[3], bf[p][2], bf[p][3]);
            }
        }
    }

    // token stats
    atomicAdd(&sumS[qi * 2],     s1a); atomicAdd(&sqS[qi * 2],     s2a);
    atomicAdd(&sumS[qi * 2 + 1], s1b); atomicAdd(&sqS[qi * 2 + 1], s2b);
    __syncthreads();
    if (t < 128) {
        float mu  = sumS[t] * (1.f / DIM);
        float var = sqS[t] * (1.f / DIM) - mu * mu;
        float r   = rsqrtf(var + EPS_LN);
        muS[t] = mu; rS[t] = r;
        g_mu[b * HW + q0 + t] = mu;
        g_r [b * HW + q0 + t] = r;
    }
    __syncthreads();

    // epilogue: y -> gelu -> logits
#pragma unroll
    for (int mt = 0; mt < 2; mt++) {
#pragma unroll
        for (int hf = 0; hf < 2; hf++) {
            int ql   = wm * 32 + mt * 16 + hf * 8 + gid;
            float mu = muS[ql], r = rS[ql];
            float pl[NTOK];
#pragma unroll
            for (int n = 0; n < NTOK; n++) pl[n] = 0.f;
#pragma unroll
            for (int nt = 0; nt < 6; nt++) {
#pragma unroll
                for (int ch = 0; ch < 2; ch++) {
                    int i   = wn * 48 + nt * 8 + tid * 2 + ch;
                    float v = acc[mt][nt][hf * 2 + ch];
                    float y = r * (v - mu * colsumS[i]) + bw1S[i];
                    float h = 0.5f * y * (1.f + erff(y * 0.70710678f));
#pragma unroll
                    for (int n = 0; n < NTOK; n++) pl[n] += h * w2S[i * NTOK + n];
                }
            }
#pragma unroll
            for (int n = 0; n < NTOK; n++) {
                pl[n] += __shfl_xor_sync(0xffffffffu, pl[n], 1);
                pl[n] += __shfl_xor_sync(0xffffffffu, pl[n], 2);
            }
            if (tid == 0) {
#pragma unroll
                for (int n = 0; n < NTOK; n++)
                    atomicAdd(&logitsS[ql * NTOK + n], pl[n]);
            }
        }
    }
    __syncthreads();
    for (int idx = t; idx < 128 * NTOK; idx += 256) {
        int n = idx >> 7, q = idx & 127;
        g_logitsT[((size_t)b * NTOK + n) * HW + q0 + q] = logitsS[q * NTOK + n];
    }
}

// ---------------- pass B: softmax; emit split-bf16 weights -------------------
__global__ void passB_kernel()
{
    int b = blockIdx.x;
    int w = threadIdx.x >> 5, lane = threadIdx.x & 31;
    const float* lp  = g_logitsT + ((size_t)b * NTOK + w) * HW;
    const float* mup = g_mu + (size_t)b * HW;
    const float* rp  = g_r  + (size_t)b * HW;

    float m = -1e30f;
    for (int j = 0; j < 32; j++) m = fmaxf(m, lp[lane + j * 32]);
#pragma unroll
    for (int o = 16; o; o >>= 1) m = fmaxf(m, __shfl_xor_sync(0xffffffffu, m, o));

    float Z = 0.f, Sm = 0.f;
    for (int j = 0; j < 32; j++) {
        int p  = lane + j * 32;
        float e = expf(lp[p] - m);
        Z  += e;
        Sm += mup[p] * rp[p] * e;
    }
#pragma unroll
    for (int o = 16; o; o >>= 1) {
        Z  += __shfl_xor_sync(0xffffffffu, Z,  o);
        Sm += __shfl_xor_sync(0xffffffffu, Sm, o);
    }
    float invZ = 1.f / Z;
    __nv_bfloat16* hp  = g_awH + ((size_t)b * NTOK + w) * HW;
    __nv_bfloat16* lpv = g_awL + ((size_t)b * NTOK + w) * HW;
    for (int j = 0; j < 32; j++) {
        int p   = lane + j * 32;
        float e = expf(lp[p] - m);
        float v = rp[p] * e * invZ;
        __nv_bfloat16 h = __float2bfloat16(v);
        __nv_bfloat16 l = __float2bfloat16(v - __bfloat162float(h));
        hp[p]  = h;
        lpv[p] = l;
    }
    if (lane == 0) g_S[b * NTOK + w] = Sm * invZ;
}

// ---------------- pass C: register-direct MMA, pre-split B, full K -----------
struct KData { float2 a0, a1, a2, a3; uint32_t bh0, bh1, bl0, bl1; };

__device__ __forceinline__ void ld_k(KData& d, const float* xr, const float* xr8,
                                     const __nv_bfloat16* brH,
                                     const __nv_bfloat16* brL, int k0)
{
    d.a0  = *(const float2*)(xr  + k0);
    d.a1  = *(const float2*)(xr8 + k0);
    d.a2  = *(const float2*)(xr  + k0 + 8);
    d.a3  = *(const float2*)(xr8 + k0 + 8);
    d.bh0 = *(const uint32_t*)(brH + k0);
    d.bh1 = *(const uint32_t*)(brH + k0 + 8);
    d.bl0 = *(const uint32_t*)(brL + k0);
    d.bl1 = *(const uint32_t*)(brL + k0 + 8);
}

__global__ __launch_bounds__(256) void passC_kernel(
    const float* __restrict__ x, const float* __restrict__ gamma,
    const float* __restrict__ beta, float* __restrict__ out)
{
    int t = threadIdx.x, w = t >> 5, lane = t & 31;
    int blk  = blockIdx.x;
    int b    = blk / 6;
    int slab = blk % 6;

    int g  = lane >> 2;          // row-group (A rows / B col n)
    int tq = (lane & 3) * 2;     // k-pair offset

    int cw = slab * 128 + w * 16;
    const float* xr  = x + ((size_t)b * DIM + cw + g) * HW + tq;
    const float* xr8 = xr + 8 * HW;
    const __nv_bfloat16* brH = g_awH + ((size_t)b * NTOK + g) * HW + tq;
    const __nv_bfloat16* brL = g_awL + ((size_t)b * NTOK + g) * HW + tq;

    float acc[4]  = {0.f, 0.f, 0.f, 0.f};
    float acc2[4] = {0.f, 0.f, 0.f, 0.f};

    KData buf[2];
    ld_k(buf[0], xr, xr8, brH, brL, 0);
    ld_k(buf[1], xr, xr8, brH, brL, 16);

#pragma unroll 2
    for (int ks = 0; ks < 64; ks++) {
        KData cur = buf[ks & 1];
        if (ks < 62) ld_k(buf[ks & 1], xr, xr8, brH, brL, (ks + 2) * 16);

        uint32_t ah0, ah1, ah2, ah3, al0, al1, al2, al3;
        split2(cur.a0, ah0, al0);
        split2(cur.a1, ah1, al1);
        split2(cur.a2, ah2, al2);
        split2(cur.a3, ah3, al3);

        mma_bf16(acc,  ah0, ah1, ah2, ah3, cur.bh0, cur.bh1);
        mma_bf16(acc2, ah0, ah1, ah2, ah3, cur.bl0, cur.bl1);
        mma_bf16(acc,  al0, al1, al2, al3, cur.bh0, cur.bh1);
    }

    int n0 = (lane & 3) * 2;
    float S0 = g_S[b * NTOK + n0];
    float S1 = g_S[b * NTOK + n0 + 1];
    int m0 = lane >> 2;
#pragma unroll
    for (int half = 0; half < 2; half++) {
        int c = cw + m0 + half * 8;
        float gm = gamma[c], be = beta[c];
        float v0 = acc[half * 2 + 0] + acc2[half * 2 + 0];
        float v1 = acc[half * 2 + 1] + acc2[half * 2 + 1];
        float2 o;
        o.x = (gm * (v0 - S0) + be) * (1.f / 1024.f);
        o.y = (gm * (v1 - S1) + be) * (1.f / 1024.f);
        *(float2*)&out[(((size_t)b * DIM) + c) * NTOK + n0] = o;
    }
}

// ---------------- launcher ----------------------------------------------------
extern "C" void kernel_launch(void* const* d_in, const int* in_sizes, int n_in,
                              void* d_out, int out_size)
{
    const float* x     = (const float*)d_in[0];
    const float* gamma = (const float*)d_in[1];
    const float* beta  = (const float*)d_in[2];
    const float* w1    = (const float*)d_in[3];
    const float* b1    = (const float*)d_in[4];
    const float* w2    = (const float*)d_in[5];
    // d_in[6] = b2: constant shift before token softmax -> cancels exactly.
    float* out = (float*)d_out;

    setup_kernel<<<INNER, 256>>>(w1, gamma, beta, b1);
    passA_kernel<<<NB * 8, 256>>>(x, w2);
    passB_kernel<<<NB, 256>>>();
    passC_kernel<<<NB * 6, 256>>>(x, gamma, beta, out);
}

// round 17
// speedup vs baseline: 1.4303x; 1.0922x over previous
#include <cuda_runtime.h>
#include <cuda_bf16.h>
#include <cstdint>

#define DIM   768
#define INNER 96
#define NTOK  8
#define HW    1024
#define NB    64
#define EPS_LN 1e-5f

typedef unsigned long long ull;

// ---------------- scratch (device globals; no allocation allowed) ------------
__device__ __nv_bfloat16 g_Wt[INNER * DIM];        // W1*gamma, bf16, [i][c]
__device__ float g_colsum[INNER];
__device__ float g_bw1[INNER];
__device__ float g_r[NB * HW];
__device__ float g_mu[NB * HW];
__device__ float g_logitsT[NB * NTOK * HW];
__device__ float g_attnwT[NB * NTOK * HW];         // r_p * attn[p,n], [b][n][p]
__device__ float g_S[NB * NTOK];

// ---------------- helpers ----------------------------------------------------
__device__ __forceinline__ void mma_bf16(float* d,
    uint32_t a0, uint32_t a1, uint32_t a2, uint32_t a3,
    uint32_t b0, uint32_t b1)
{
    asm volatile(
        "mma.sync.aligned.m16n8k16.row.col.f32.bf16.bf16.f32 "
        "{%0,%1,%2,%3}, {%4,%5,%6,%7}, {%8,%9}, {%0,%1,%2,%3};"
        : "+f"(d[0]), "+f"(d[1]), "+f"(d[2]), "+f"(d[3])
        : "r"(a0), "r"(a1), "r"(a2), "r"(a3), "r"(b0), "r"(b1));
}

__device__ __forceinline__ void ldsm_x4(uint32_t* r, uint32_t addr) {
    asm volatile("ldmatrix.sync.aligned.m8n8.x4.shared.b16 {%0,%1,%2,%3}, [%4];"
        : "=r"(r[0]), "=r"(r[1]), "=r"(r[2]), "=r"(r[3]) : "r"(addr));
}

// split fp32 pair -> hi bf16x2 + residual bf16x2
__device__ __forceinline__ void split2(float2 v, uint32_t& h, uint32_t& l) {
    __nv_bfloat162 hb = __floats2bfloat162_rn(v.x, v.y);
    uint32_t hu = *(uint32_t*)&hb;
    float f0 = __uint_as_float(hu << 16);
    float f1 = __uint_as_float(hu & 0xffff0000u);
    __nv_bfloat162 lb = __floats2bfloat162_rn(v.x - f0, v.y - f1);
    h = hu; l = *(uint32_t*)&lb;
}

// ---------------- setup: fold gamma into W1, precompute column sums ----------
__global__ void setup_kernel(const float* __restrict__ w1,
                             const float* __restrict__ gamma,
                             const float* __restrict__ beta,
                             const float* __restrict__ b1)
{
    int i = blockIdx.x;
    int t = threadIdx.x;
    float a = 0.f, bs = 0.f;
    for (int c = t; c < DIM; c += 256) {
        float w  = w1[c * INNER + i];
        float gw = gamma[c] * w;
        g_Wt[i * DIM + c] = __float2bfloat16(gw);
        a  += gw;
        bs += beta[c] * w;
    }
    __shared__ float ra[256], rb[256];
    ra[t] = a; rb[t] = bs;
    __syncthreads();
    for (int s = 128; s > 0; s >>= 1) {
        if (t < s) { ra[t] += ra[t + s]; rb[t] += rb[t + s]; }
        __syncthreads();
    }
    if (t == 0) { g_colsum[i] = ra[0]; g_bw1[i] = rb[0] + b1[i]; }
}

// ---------------- pass A: R12 geometry + 2-deep register prefetch ------------
constexpr int XP = 40;
constexpr int WP = 40;

__global__ __launch_bounds__(256, 2) void passA_kernel(
    const float* __restrict__ x, const float* __restrict__ w2)
{
    __shared__ __nv_bfloat16 Xs[2][128 * XP];
    __shared__ __nv_bfloat16 Ws[2][INNER * WP];
    __shared__ float logitsS[128 * NTOK];
    __shared__ float sumS[128], sqS[128], muS[128], rS[128];
    __shared__ float w2S[INNER * NTOK];
    __shared__ float colsumS[INNER], bw1S[INNER];

    int t   = threadIdx.x;
    int blk = blockIdx.x;
    int b   = blk >> 3;
    int q0  = (blk & 7) << 7;

    for (int i = t; i < 128 * NTOK; i += 256) logitsS[i] = 0.f;
    if (t < 128) { sumS[t] = 0.f; sqS[t] = 0.f; }
    for (int i = t; i < INNER * NTOK; i += 256) w2S[i] = w2[i];
    if (t < INNER) { colsumS[t] = g_colsum[t]; bw1S[t] = g_bw1[t]; }

    int qi = t & 63;           // token pair: rows 2qi, 2qi+1
    int ci = t >> 6;           // channel slice 0..3 (8 channels each)
    const float* xb = x + ((size_t)b * DIM) * HW + q0 + qi * 2;

    float s1a = 0.f, s1b = 0.f, s2a = 0.f, s2b = 0.f;
    float acc[2][6][4];
#pragma unroll
    for (int mt = 0; mt < 2; mt++)
#pragma unroll
        for (int nt = 0; nt < 6; nt++)
#pragma unroll
            for (int r = 0; r < 4; r++) acc[mt][nt][r] = 0.f;

    int w    = t >> 5, lane = t & 31;
    int wm   = w & 3,  wn   = w >> 2;   // warp tile: 32 tok x 48 i
    int gid  = lane >> 2, tid = lane & 3;
    int wi   = t >> 1, whf = t & 1;     // W loader (t<192): row wi, 16-ch half

    uint32_t aAddr0 = (uint32_t)__cvta_generic_to_shared(
        &Xs[0][(wm * 32 + (lane & 15)) * XP + (lane >> 4) * 8]);
    uint32_t aAddr1 = aAddr0 + 16 * XP * 2;
    // B ldmatrix.x4: lanes 0-7 -> [n0..7, k0-7], 8-15 -> [n0..7, k8-15],
    //                16-23 -> [n8..15, k0-7], 24-31 -> [n8..15, k8-15]
    uint32_t bAddr4 = (uint32_t)__cvta_generic_to_shared(
        &Ws[0][(wn * 48 + (lane >> 4) * 8 + (lane & 7)) * WP + ((lane >> 3) & 1) * 8]);
    const uint32_t XBUF = 128 * XP * 2;
    const uint32_t WBUF = INNER * WP * 2;

    // two-deep register prefetch: stage s holds chunk (kc+s) at iter kc
    float2 xv[2][8];
    uint4 wv[2][2];
#pragma unroll
    for (int s = 0; s < 2; s++) {
        int c0 = s * 32;
#pragma unroll
        for (int j = 0; j < 8; j++)
            xv[s][j] = *(const float2*)(xb + (size_t)(c0 + ci * 8 + j) * HW);
        if (t < 192) {
            const uint4* src = (const uint4*)(g_Wt + wi * DIM + c0 + whf * 16);
            wv[s][0] = src[0]; wv[s][1] = src[1];
        }
    }

#pragma unroll 2
    for (int kc = 0; kc < 24; kc++) {
        int buf = kc & 1;           // also the register stage holding chunk kc
#pragma unroll
        for (int j = 0; j < 8; j++) {
            s1a += xv[buf][j].x; s2a += xv[buf][j].x * xv[buf][j].x;
            s1b += xv[buf][j].y; s2b += xv[buf][j].y * xv[buf][j].y;
        }
        __nv_bfloat162 p0[4], p1[4];
#pragma unroll
        for (int j = 0; j < 4; j++) {
            p0[j] = __floats2bfloat162_rn(xv[buf][2*j].x, xv[buf][2*j+1].x);
            p1[j] = __floats2bfloat162_rn(xv[buf][2*j].y, xv[buf][2*j+1].y);
        }
        *(uint4*)&Xs[buf][(qi * 2)     * XP + ci * 8] = *(uint4*)p0;
        *(uint4*)&Xs[buf][(qi * 2 + 1) * XP + ci * 8] = *(uint4*)p1;
        if (t < 192) {
            uint4* dst = (uint4*)&Ws[buf][wi * WP + whf * 16];
            dst[0] = wv[buf][0]; dst[1] = wv[buf][1];
        }

        // refill the consumed stage with chunk kc+2 (2 iterations of cover)
        if (kc < 22) {
            int c0 = (kc + 2) * 32;
#pragma unroll
            for (int j = 0; j < 8; j++)
                xv[buf][j] = *(const float2*)(xb + (size_t)(c0 + ci * 8 + j) * HW);
            if (t < 192) {
                const uint4* src = (const uint4*)(g_Wt + wi * DIM + c0 + whf * 16);
                wv[buf][0] = src[0]; wv[buf][1] = src[1];
            }
        }
        __syncthreads();

        uint32_t xo = buf * XBUF, wo = buf * WBUF;
#pragma unroll
        for (int ks = 0; ks < 2; ks++) {
            uint32_t af0[4], af1[4];
            ldsm_x4(af0, aAddr0 + xo + ks * 32);
            ldsm_x4(af1, aAddr1 + xo + ks * 32);
            uint32_t bf[3][4];
#pragma unroll
            for (int p = 0; p < 3; p++)
                ldsm_x4(bf[p], bAddr4 + wo + p * 16 * WP * 2 + ks * 32);
#pragma unroll
            for (int p = 0; p < 3; p++) {
                mma_bf16(acc[0][2*p],   af0[0], af0[1], af0[2], af0[3], bf[p][0], bf[p][1]);
                mma_bf16(acc[1][2*p],   af1[0], af1[1], af1[2], af1[3], bf[p][0], bf[p][1]);
                mma_bf16(acc[0][2*p+1], af0[0], af0[1], af0[2], af0[3], bf[p][2], bf[p][3]);
                mma_bf16(acc[1][2*p+1], af1[0], af1[1], af1[2], af1[3], bf[p][2], bf[p][3]);
            }
        }
    }

    // token stats
    atomicAdd(&sumS[qi * 2],     s1a); atomicAdd(&sqS[qi * 2],     s2a);
    atomicAdd(&sumS[qi * 2 + 1], s1b); atomicAdd(&sqS[qi * 2 + 1], s2b);
    __syncthreads();
    if (t < 128) {
        float mu  = sumS[t] * (1.f / DIM);
        float var = sqS[t] * (1.f / DIM) - mu * mu;
        float r   = rsqrtf(var + EPS_LN);
        muS[t] = mu; rS[t] = r;
        g_mu[b * HW + q0 + t] = mu;
        g_r [b * HW + q0 + t] = r;
    }
    __syncthreads();

    // epilogue: y -> gelu -> logits
#pragma unroll
    for (int mt = 0; mt < 2; mt++) {
#pragma unroll
        for (int hf = 0; hf < 2; hf++) {
            int ql   = wm * 32 + mt * 16 + hf * 8 + gid;
            float mu = muS[ql], r = rS[ql];
            float pl[NTOK];
#pragma unroll
            for (int n = 0; n < NTOK; n++) pl[n] = 0.f;
#pragma unroll
            for (int nt = 0; nt < 6; nt++) {
#pragma unroll
                for (int ch = 0; ch < 2; ch++) {
                    int i   = wn * 48 + nt * 8 + tid * 2 + ch;
                    float v = acc[mt][nt][hf * 2 + ch];
                    float y = r * (v - mu * colsumS[i]) + bw1S[i];
                    float h = 0.5f * y * (1.f + erff(y * 0.70710678f));
#pragma unroll
                    for (int n = 0; n < NTOK; n++) pl[n] += h * w2S[i * NTOK + n];
                }
            }
#pragma unroll
            for (int n = 0; n < NTOK; n++) {
                pl[n] += __shfl_xor_sync(0xffffffffu, pl[n], 1);
                pl[n] += __shfl_xor_sync(0xffffffffu, pl[n], 2);
            }
            if (tid == 0) {
#pragma unroll
                for (int n = 0; n < NTOK; n++)
                    atomicAdd(&logitsS[ql * NTOK + n], pl[n]);
            }
        }
    }
    __syncthreads();
    for (int idx = t; idx < 128 * NTOK; idx += 256) {
        int n = idx >> 7, q = idx & 127;
        g_logitsT[((size_t)b * NTOK + n) * HW + q0 + q] = logitsS[q * NTOK + n];
    }
}

// ---------------- pass B: softmax over tokens, per (b, n) --------------------
__global__ void passB_kernel()
{
    int b = blockIdx.x;
    int w = threadIdx.x >> 5, lane = threadIdx.x & 31;
    const float* lp  = g_logitsT + ((size_t)b * NTOK + w) * HW;
    const float* mup = g_mu + (size_t)b * HW;
    const float* rp  = g_r  + (size_t)b * HW;

    float m = -1e30f;
    for (int j = 0; j < 32; j++) m = fmaxf(m, lp[lane + j * 32]);
#pragma unroll
    for (int o = 16; o; o >>= 1) m = fmaxf(m, __shfl_xor_sync(0xffffffffu, m, o));

    float Z = 0.f, Sm = 0.f;
    for (int j = 0; j < 32; j++) {
        int p  = lane + j * 32;
        float e = expf(lp[p] - m);
        Z  += e;
        Sm += mup[p] * rp[p] * e;
    }
#pragma unroll
    for (int o = 16; o; o >>= 1) {
        Z  += __shfl_xor_sync(0xffffffffu, Z,  o);
        Sm += __shfl_xor_sync(0xffffffffu, Sm, o);
    }
    float invZ = 1.f / Z;
    float* ap = g_attnwT + ((size_t)b * NTOK + w) * HW;
    for (int j = 0; j < 32; j++) {
        int p  = lane + j * 32;
        float e = expf(lp[p] - m);
        ap[p] = rp[p] * e * invZ;
    }
    if (lane == 0) g_S[b * NTOK + w] = Sm * invZ;
}

// ---------------- pass C (R7 form): register-direct split-bf16 MMA -----------
struct KData { float2 a0, a1, a2, a3, b0, b1; };

__device__ __forceinline__ void ld_k(KData& d, const float* xr, const float* xr8,
                                     const float* br, int k0)
{
    d.a0 = *(const float2*)(xr  + k0);
    d.a1 = *(const float2*)(xr8 + k0);
    d.a2 = *(const float2*)(xr  + k0 + 8);
    d.a3 = *(const float2*)(xr8 + k0 + 8);
    d.b0 = *(const float2*)(br  + k0);
    d.b1 = *(const float2*)(br  + k0 + 8);
}

__global__ __launch_bounds__(256) void passC_kernel(
    const float* __restrict__ x, const float* __restrict__ gamma,
    const float* __restrict__ beta, float* __restrict__ out)
{
    int t = threadIdx.x, w = t >> 5, lane = t & 31;
    int blk  = blockIdx.x;
    int b    = blk / 6;
    int slab = blk % 6;

    int g  = lane >> 2;          // row-group (A rows / B col n)
    int tq = (lane & 3) * 2;     // k-pair offset

    int cw = slab * 128 + w * 16;
    const float* xr  = x + ((size_t)b * DIM + cw + g) * HW + tq;
    const float* xr8 = xr + 8 * HW;
    const float* br  = g_attnwT + ((size_t)b * NTOK + g) * HW + tq;

    float acc[4]  = {0.f, 0.f, 0.f, 0.f};
    float acc2[4] = {0.f, 0.f, 0.f, 0.f};

    KData buf[2];
    ld_k(buf[0], xr, xr8, br, 0);
    ld_k(buf[1], xr, xr8, br, 16);

#pragma unroll 2
    for (int ks = 0; ks < 64; ks++) {
        KData cur = buf[ks & 1];
        if (ks < 62) ld_k(buf[ks & 1], xr, xr8, br, (ks + 2) * 16);

        uint32_t ah0, ah1, ah2, ah3, al0, al1, al2, al3;
        uint32_t bh0, bh1, bl0, bl1;
        split2(cur.a0, ah0, al0);
        split2(cur.a1, ah1, al1);
        split2(cur.a2, ah2, al2);
        split2(cur.a3, ah3, al3);
        split2(cur.b0, bh0, bl0);
        split2(cur.b1, bh1, bl1);

        mma_bf16(acc,  ah0, ah1, ah2, ah3, bh0, bh1);
        mma_bf16(acc2, ah0, ah1, ah2, ah3, bl0, bl1);
        mma_bf16(acc,  al0, al1, al2, al3, bh0, bh1);
    }

    int n0 = (lane & 3) * 2;
    float S0 = g_S[b * NTOK + n0];
    float S1 = g_S[b * NTOK + n0 + 1];
    int m0 = lane >> 2;
#pragma unroll
    for (int half = 0; half < 2; half++) {
        int c = cw + m0 + half * 8;
        float gm = gamma[c], be = beta[c];
        float v0 = acc[half * 2 + 0] + acc2[half * 2 + 0];
        float v1 = acc[half * 2 + 1] + acc2[half * 2 + 1];
        float2 o;
        o.x = (gm * (v0 - S0) + be) * (1.f / 1024.f);
        o.y = (gm * (v1 - S1) + be) * (1.f / 1024.f);
        *(float2*)&out[(((size_t)b * DIM) + c) * NTOK + n0] = o;
    }
}

// ---------------- launcher ----------------------------------------------------
extern "C" void kernel_launch(void* const* d_in, const int* in_sizes, int n_in,
                              void* d_out, int out_size)
{
    const float* x     = (const float*)d_in[0];
    const float* gamma = (const float*)d_in[1];
    const float* beta  = (const float*)d_in[2];
    const float* w1    = (const float*)d_in[3];
    const float* b1    = (const float*)d_in[4];
    const float* w2    = (const float*)d_in[5];
    // d_in[6] = b2: constant shift before token softmax -> cancels exactly.
    float* out = (float*)d_out;

    setup_kernel<<<INNER, 256>>>(w1, gamma, beta, b1);
    passA_kernel<<<NB * 8, 256>>>(x, w2);
    passB_kernel<<<NB, 256>>>();
    passC_kernel<<<NB * 6, 256>>>(x, gamma, beta, out);
}